// round 5
// baseline (speedup 1.0000x reference)
#include <cuda_runtime.h>

#define BB 64
#define TT 1024
#define NN 48
#define TM1 1023
#define NCHUNK 16
#define TPC 64

// Scratch (device globals — no allocation allowed)
__device__ float g_wmat[BB * TT * NN];   // exp(y_pred - row max)
__device__ float g_mu[BB * TT];          // per-row max of y_pred
__device__ float g_partials[BB * NCHUNK];// point+trans partial sums

// ---------------------------------------------------------------------------
// Kernel 1: parallel part. Per (b,t):
//  - row max mu and w = exp(yp - mu)  (for the scan kernel)
//  - point score  sum_n yp*yt
//  - trans score  l1^T TRANS[k] l2  (t < 1023)
// grid (B, NCHUNK), block 256 (8 warps, each warp owns 8 consecutive t)
// ---------------------------------------------------------------------------
__global__ __launch_bounds__(256) void scores_kernel(
    const float* __restrict__ yt, const float* __restrict__ yp,
    const int* __restrict__ spk,
    const float* __restrict__ tr0, const float* __restrict__ tr1,
    const float* __restrict__ tr2)
{
    __shared__ float sT[3 * NN * NN];
    __shared__ float ybuf[8][2][NN];
    __shared__ float swarp[8];

    const int b = blockIdx.x, ch = blockIdx.y;
    const int tid = threadIdx.x, w = tid >> 5, l = tid & 31;

    for (int i = tid; i < NN * NN; i += 256) {
        sT[i]              = tr0[i];
        sT[NN * NN + i]    = tr1[i];
        sT[2 * NN * NN + i] = tr2[i];
    }

    const int tbase = ch * TPC + w * 8;
    const float* ytb = yt + (size_t)b * TT * NN;
    const float* ypb = yp + (size_t)b * TT * NN;

    // preload l1 = y_true[b, tbase]
    ybuf[w][0][l] = ytb[tbase * NN + l];
    if (l < 16) ybuf[w][0][32 + l] = ytb[tbase * NN + 32 + l];
    __syncthreads();

    float acc = 0.0f;
    #pragma unroll 1
    for (int tt = 0; tt < 8; tt++) {
        const int t = tbase + tt;
        const int cur = tt & 1, nxt = cur ^ 1;

        // ---- y_pred row: max, w, point ----
        float y1 = ypb[t * NN + l];
        float y2 = (l < 16) ? ypb[t * NN + 32 + l] : -3.0e38f;
        float m = fmaxf(y1, y2);
        m = fmaxf(m, __shfl_xor_sync(0xffffffffu, m, 16));
        m = fmaxf(m, __shfl_xor_sync(0xffffffffu, m, 8));
        m = fmaxf(m, __shfl_xor_sync(0xffffffffu, m, 4));
        m = fmaxf(m, __shfl_xor_sync(0xffffffffu, m, 2));
        m = fmaxf(m, __shfl_xor_sync(0xffffffffu, m, 1));
        g_wmat[((size_t)b * TT + t) * NN + l] = __expf(y1 - m);
        if (l < 16) g_wmat[((size_t)b * TT + t) * NN + 32 + l] = __expf(y2 - m);
        if (l == 0) g_mu[b * TT + t] = m;

        float t1a = ybuf[w][cur][l];
        acc += y1 * t1a;
        if (l < 16) acc += y2 * ybuf[w][cur][32 + l];

        // ---- transition score ----
        if (t < TM1) {
            float l2a = ytb[(t + 1) * NN + l];
            ybuf[w][nxt][l] = l2a;
            float l2b = 0.0f;
            if (l < 16) { l2b = ytb[(t + 1) * NN + 32 + l]; ybuf[w][nxt][32 + l] = l2b; }
            __syncwarp();
            const int k = spk[b * TM1 + t];
            const float* Tk = sT + k * NN * NN;
            float va = 0.0f, vb = 0.0f;
            #pragma unroll 8
            for (int i = 0; i < NN; i++) {
                float a = ybuf[w][cur][i];
                va += a * Tk[i * NN + l];
                if (l < 16) vb += a * Tk[i * NN + 32 + l];
            }
            acc += va * l2a + vb * l2b;
        }
        __syncwarp();
    }

    // warp reduce then block reduce
    for (int o = 16; o; o >>= 1) acc += __shfl_xor_sync(0xffffffffu, acc, o);
    if (l == 0) swarp[w] = acc;
    __syncthreads();
    if (tid == 0) {
        float s = 0.0f;
        #pragma unroll
        for (int i = 0; i < 8; i++) s += swarp[i];
        g_partials[b * NCHUNK + ch] = s;
    }
}

// ---------------------------------------------------------------------------
// Kernel 2: forward scan. One CTA per batch, 96 threads.
// thread (j = w*16 + l%16, h = l/16) computes i in [h*24, h*24+24) of the
// matvec acc_j = sum_i p_i * exp(T[k])_{i,j}, E columns live in REGISTERS.
// Normalization: p' = acc * w * (1/p0_prev); exact bookkeeping in c.
// ---------------------------------------------------------------------------
__global__ __launch_bounds__(96) void scan_kernel(
    const int* __restrict__ spk,
    const float* __restrict__ tr0, const float* __restrict__ tr1,
    const float* __restrict__ tr2,
    float* __restrict__ out)
{
    __shared__ float sp[2][NN];
    __shared__ int sspk[TM1 + 1];

    const int b = blockIdx.x;
    const int tid = threadIdx.x, w = tid >> 5, l = tid & 31;
    const int j = w * 16 + (l & 15);
    const int h = l >> 4;
    const int ibase = h * 24;

    // E columns in registers: E[k][ibase+ii][j]
    float E0[24], E1[24], E2[24];
    #pragma unroll
    for (int ii = 0; ii < 24; ii++) {
        const int idx = (ibase + ii) * NN + j;
        E0[ii] = __expf(tr0[idx]);
        E1[ii] = __expf(tr1[idx]);
        E2[ii] = __expf(tr2[idx]);
    }

    for (int i = tid; i < TM1; i += 96) sspk[i] = spk[b * TM1 + i];

    const float* wb  = g_wmat + (size_t)b * TT * NN;
    const float* mub = g_mu + b * TT;

    if (h == 0) sp[0][j] = wb[j];       // p(0) = exp(yp[b,0,:] - mu0)
    float c = mub[0];

    // prefetch w,mu two steps ahead
    float w1 = wb[1 * NN + j], m1 = mub[1];
    float w2 = wb[2 * NN + j], m2 = mub[2];
    __syncthreads();

    #pragma unroll 1
    for (int t = 1; t < TT; t++) {
        const int s = (t - 1) & 1;
        const int k = sspk[t - 1];

        const float p0 = sp[s][0];
        const float rinv = __fdividef(1.0f, p0);

        float pr[24];
        #pragma unroll
        for (int q = 0; q < 6; q++) {
            float4 v = *(const float4*)&sp[s][ibase + 4 * q];
            pr[4 * q + 0] = v.x; pr[4 * q + 1] = v.y;
            pr[4 * q + 2] = v.z; pr[4 * q + 3] = v.w;
        }

        float a0 = 0.f, a1 = 0.f, a2 = 0.f, a3 = 0.f;
#define DOT24(EA) do { \
        _Pragma("unroll") \
        for (int q = 0; q < 6; q++) { \
            a0 += pr[4*q+0] * EA[4*q+0]; \
            a1 += pr[4*q+1] * EA[4*q+1]; \
            a2 += pr[4*q+2] * EA[4*q+2]; \
            a3 += pr[4*q+3] * EA[4*q+3]; \
        } } while (0)
        if (k == 0)      DOT24(E0);
        else if (k == 1) DOT24(E1);
        else             DOT24(E2);
#undef DOT24
        const float partial = (a0 + a1) + (a2 + a3);
        const float accj = partial + __shfl_xor_sync(0xffffffffu, partial, 16);

        const float pn = accj * w1 * rinv;
        if (h == 0) sp[s ^ 1][j] = pn;

        c += m1 + __logf(p0);           // off the critical path

        w1 = w2; m1 = m2;
        if (t + 2 < TT) { w2 = wb[(t + 2) * NN + j]; m2 = mub[t + 2]; }
        __syncthreads();
    }

    if (tid == 0) {
        float sum = 0.0f;
        #pragma unroll
        for (int jj = 0; jj < NN; jj++) sum += sp[1][jj];
        float sc = 0.0f;
        #pragma unroll
        for (int i = 0; i < NCHUNK; i++) sc += g_partials[b * NCHUNK + i];
        out[b] = c + __logf(sum) - sc;
    }
}

extern "C" void kernel_launch(void* const* d_in, const int* in_sizes, int n_in,
                              void* d_out, int out_size)
{
    const float* yt  = (const float*)d_in[0];
    const float* yp  = (const float*)d_in[1];
    const int*   spk = (const int*)d_in[2];
    const float* t0  = (const float*)d_in[3];
    const float* t1  = (const float*)d_in[4];
    const float* t2  = (const float*)d_in[5];
    float* out = (float*)d_out;

    dim3 g(BB, NCHUNK);
    scores_kernel<<<g, 256>>>(yt, yp, spk, t0, t1, t2);
    scan_kernel<<<BB, 96>>>(spk, t0, t1, t2, out);
}

// round 6
// speedup vs baseline: 2.2431x; 2.2431x over previous
#include <cuda_runtime.h>

#define BB 64
#define TT 1024
#define NN 48
#define TM1 1023
#define NCHUNK 16
#define TPC 64

// Scratch (device globals — zero-initialized at load; no allocation allowed)
__device__ float g_ws[BB * NN * TT];      // ws[b][j][s] = exp(yp[b,s+1,j]-mu(s+1)); s=t-1. [*,*,1023] stays 0 (pad)
__device__ float g_w0[BB * NN];           // p(0) = exp(yp[b,0,:]-mu0)
__device__ float g_partials[BB * NCHUNK]; // point+trans partial sums
__device__ float g_partmu[BB * NCHUNK];   // partial sums of per-row max mu

// ---------------------------------------------------------------------------
// Kernel 1: parallel part. Per (b,t): row max mu, w=exp(yp-mu) stored
// TRANSPOSED as ws[b][j][t-1]; point score; trans score; and sum of mu.
// ---------------------------------------------------------------------------
__global__ __launch_bounds__(256) void scores_kernel(
    const float* __restrict__ yt, const float* __restrict__ yp,
    const int* __restrict__ spk,
    const float* __restrict__ tr0, const float* __restrict__ tr1,
    const float* __restrict__ tr2)
{
    __shared__ float sT[3 * NN * NN];
    __shared__ float ybuf[8][2][NN];
    __shared__ float swarp[8];
    __shared__ float swarpmu[8];

    const int b = blockIdx.x, ch = blockIdx.y;
    const int tid = threadIdx.x, w = tid >> 5, l = tid & 31;

    for (int i = tid; i < NN * NN; i += 256) {
        sT[i]               = tr0[i];
        sT[NN * NN + i]     = tr1[i];
        sT[2 * NN * NN + i] = tr2[i];
    }

    const int tbase = ch * TPC + w * 8;
    const float* ytb = yt + (size_t)b * TT * NN;
    const float* ypb = yp + (size_t)b * TT * NN;

    // preload l1 = y_true[b, tbase]
    ybuf[w][0][l] = ytb[tbase * NN + l];
    if (l < 16) ybuf[w][0][32 + l] = ytb[tbase * NN + 32 + l];
    __syncthreads();

    float acc = 0.0f;
    float accmu = 0.0f;
    #pragma unroll 1
    for (int tt = 0; tt < 8; tt++) {
        const int t = tbase + tt;
        const int cur = tt & 1, nxt = cur ^ 1;

        // ---- y_pred row: max, w, point ----
        float y1 = ypb[t * NN + l];
        float y2 = (l < 16) ? ypb[t * NN + 32 + l] : -3.0e38f;
        float m = fmaxf(y1, y2);
        m = fmaxf(m, __shfl_xor_sync(0xffffffffu, m, 16));
        m = fmaxf(m, __shfl_xor_sync(0xffffffffu, m, 8));
        m = fmaxf(m, __shfl_xor_sync(0xffffffffu, m, 4));
        m = fmaxf(m, __shfl_xor_sync(0xffffffffu, m, 2));
        m = fmaxf(m, __shfl_xor_sync(0xffffffffu, m, 1));
        accmu += m;

        float e1 = __expf(y1 - m);
        if (t == 0) {
            g_w0[b * NN + l] = e1;
            if (l < 16) g_w0[b * NN + 32 + l] = __expf(y2 - m);
        } else {
            g_ws[((size_t)b * NN + l) * TT + (t - 1)] = e1;
            if (l < 16) g_ws[((size_t)b * NN + 32 + l) * TT + (t - 1)] = __expf(y2 - m);
        }

        float t1a = ybuf[w][cur][l];
        acc += y1 * t1a;
        if (l < 16) acc += y2 * ybuf[w][cur][32 + l];

        // ---- transition score ----
        if (t < TM1) {
            float l2a = ytb[(t + 1) * NN + l];
            ybuf[w][nxt][l] = l2a;
            float l2b = 0.0f;
            if (l < 16) { l2b = ytb[(t + 1) * NN + 32 + l]; ybuf[w][nxt][32 + l] = l2b; }
            __syncwarp();
            const int k = spk[b * TM1 + t];
            const float* Tk = sT + k * NN * NN;
            float va = 0.0f, vb = 0.0f;
            #pragma unroll 8
            for (int i = 0; i < NN; i++) {
                float a = ybuf[w][cur][i];
                va += a * Tk[i * NN + l];
                if (l < 16) vb += a * Tk[i * NN + 32 + l];
            }
            acc += va * l2a + vb * l2b;
        }
        __syncwarp();
    }

    // warp reduce then block reduce
    for (int o = 16; o; o >>= 1) acc += __shfl_xor_sync(0xffffffffu, acc, o);
    if (l == 0) { swarp[w] = acc; swarpmu[w] = accmu; }
    __syncthreads();
    if (tid == 0) {
        float s = 0.0f, smu = 0.0f;
        #pragma unroll
        for (int i = 0; i < 8; i++) { s += swarp[i]; smu += swarpmu[i]; }
        g_partials[b * NCHUNK + ch] = s;
        g_partmu[b * NCHUNK + ch]   = smu;
    }
}

// ---------------------------------------------------------------------------
// Kernel 2: forward scan. One CTA per batch, 96 threads (3 warps).
// thread (j = w*16 + l%16, h = l/16) computes i in [h*24, h*24+24) of the
// matvec acc_j = sum_i p_i * exp(T[k])_{i,j}; E columns in REGISTERS.
// 4-step groups: p' = (p@E)*w unnormalized for 3 steps, renorm by p0 on the
// 4th (exact bookkeeping in c). w streamed as per-thread float4 per group,
// double-buffered with prefetch distance 2 groups (8 steps).
// Runs 256 groups = steps t=1..1024; t=1024 is a phantom step (w pad = 0,
// writes only the dead buffer); its log(p0) is subtracted after the loop.
// ---------------------------------------------------------------------------
__global__ __launch_bounds__(96) void scan_kernel(
    const int* __restrict__ spk,
    const float* __restrict__ tr0, const float* __restrict__ tr1,
    const float* __restrict__ tr2,
    float* __restrict__ out)
{
    __shared__ __align__(16) float sp[2][NN];
    __shared__ __align__(16) int sspk[1032];

    const int b = blockIdx.x;
    const int tid = threadIdx.x, w = tid >> 5, l = tid & 31;
    const int j = w * 16 + (l & 15);
    const int h = l >> 4;
    const int ibase = h * 24;

    // E columns in registers: E[k][ibase+ii][j]
    float E0[24], E1[24], E2[24];
    #pragma unroll
    for (int ii = 0; ii < 24; ii++) {
        const int idx = (ibase + ii) * NN + j;
        E0[ii] = __expf(tr0[idx]);
        E1[ii] = __expf(tr1[idx]);
        E2[ii] = __expf(tr2[idx]);
    }

    for (int i = tid; i < 1032; i += 96) sspk[i] = (i < TM1) ? spk[b * TM1 + i] : 0;

    const float* wsj = g_ws + ((size_t)b * NN + j) * TT;  // this thread's w stream

    if (h == 0) sp[0][j] = g_w0[b * NN + j];
    float c = 0.0f;

    int4  kqA = *(const int4*)&sspk[0];
    float4 wA = *(const float4*)(wsj);
    float4 wB = *(const float4*)(wsj + 4);
    __syncthreads();

#define DOT24(EA) { _Pragma("unroll") \
    for (int q = 0; q < 6; q++) { \
        a0 += pr[4*q+0] * EA[4*q+0]; \
        a1 += pr[4*q+1] * EA[4*q+1]; \
        a2 += pr[4*q+2] * EA[4*q+2]; \
        a3 += pr[4*q+3] * EA[4*q+3]; \
    } }

#define DOSTEP(KK, WV, SRC, DST, NORM)                                         \
    {                                                                          \
        float p0 = 0.0f, rinv = 0.0f;                                          \
        if (NORM) {                                                            \
            p0 = sp[SRC][0];                                                   \
            asm("rcp.approx.f32 %0, %1;" : "=f"(rinv) : "f"(p0));              \
        }                                                                      \
        float pr[24];                                                          \
        _Pragma("unroll")                                                      \
        for (int q = 0; q < 6; q++) {                                          \
            float4 v = *(const float4*)&sp[SRC][ibase + 4*q];                  \
            pr[4*q+0] = v.x; pr[4*q+1] = v.y; pr[4*q+2] = v.z; pr[4*q+3] = v.w;\
        }                                                                      \
        float a0 = 0.f, a1 = 0.f, a2 = 0.f, a3 = 0.f;                          \
        if ((KK) == 0)      DOT24(E0)                                          \
        else if ((KK) == 1) DOT24(E1)                                          \
        else                DOT24(E2)                                          \
        float partial = (a0 + a1) + (a2 + a3);                                 \
        float accj = partial + __shfl_xor_sync(0xffffffffu, partial, 16);      \
        float scale = (NORM) ? ((WV) * rinv) : (WV);                           \
        if (h == 0) sp[DST][j] = accj * scale;                                 \
        if (NORM) c += __logf(p0);                                             \
        __syncthreads();                                                       \
    }

#define GROUP4(KQ, WQ)            \
    DOSTEP(KQ.x, WQ.x, 0, 1, 0)   \
    DOSTEP(KQ.y, WQ.y, 1, 0, 0)   \
    DOSTEP(KQ.z, WQ.z, 0, 1, 0)   \
    DOSTEP(KQ.w, WQ.w, 1, 0, 1)

    #pragma unroll 1
    for (int g = 0; g < 256; g += 2) {
        int4 kqB = *(const int4*)&sspk[4 * g + 4];
        GROUP4(kqA, wA)
        { int gp = g + 2; if (gp > 255) gp = 255; wA = *(const float4*)(wsj + 4 * gp); }
        GROUP4(kqB, wB)
        { int gp = g + 3; if (gp > 255) gp = 255; wB = *(const float4*)(wsj + 4 * gp); }
        kqA = *(const int4*)&sspk[4 * g + 8];
    }

    // undo the phantom step's (t=1024) log(p0): it read sp[1][0], which is intact.
    c -= __logf(sp[1][0]);

    if (tid == 0) {
        float sum = 0.0f;
        #pragma unroll
        for (int jj = 0; jj < NN; jj++) sum += sp[1][jj];
        float sc = 0.0f, smu = 0.0f;
        #pragma unroll
        for (int i = 0; i < NCHUNK; i++) {
            sc  += g_partials[b * NCHUNK + i];
            smu += g_partmu[b * NCHUNK + i];
        }
        out[b] = smu + c + __logf(sum) - sc;
    }
}

extern "C" void kernel_launch(void* const* d_in, const int* in_sizes, int n_in,
                              void* d_out, int out_size)
{
    const float* yt  = (const float*)d_in[0];
    const float* yp  = (const float*)d_in[1];
    const int*   spk = (const int*)d_in[2];
    const float* t0  = (const float*)d_in[3];
    const float* t1  = (const float*)d_in[4];
    const float* t2  = (const float*)d_in[5];
    float* out = (float*)d_out;

    dim3 g(BB, NCHUNK);
    scores_kernel<<<g, 256>>>(yt, yp, spk, t0, t1, t2);
    scan_kernel<<<BB, 96>>>(spk, t0, t1, t2, out);
}